// round 14
// baseline (speedup 1.0000x reference)
#include <cuda_runtime.h>
#include <cuda_bf16.h>

// Linear state space layer, N=512, L=16384.
// y_i = sum_{k<=i} g_{i-k} x_k + C Ab^{i+1} h0,   g_j = C Ab^j Bb
// Factorized: g_{1024q+b} = (C Ab^{1024q}) . (Ab^b Bb)
// h_L via 16-step chunk scan with Ab^1024.

static constexpr int NN = 512;     // state dim
static constexpr int SS = 1024;    // chunk size
static constexpr int QQ = 16;      // number of chunks
static constexpr int LL = 16384;   // sequence length

// ---------------- device scratch (zero-initialized at module load) -------------
__device__ float g_Ab[NN * NN];     // Ab (lower triangular)
__device__ float g_Pa[NN * NN];     // power ping
__device__ float g_Pb[NN * NN];     // power pong
__device__ float g_Pc[NN * NN];     // extra buffer for PS^m chain
__device__ float g_Bb[NN];          // Bb
__device__ float g_V[NN * SS];      // columns v_b = Ab^b Bb   (row-major N x S)
__device__ float g_W[NN * SS];      // columns w'_b = Ab^{b+1} h0
__device__ float g_R[QQ * NN];      // rows c_{1024 q} = C Ab^{1024 q}
__device__ float g_G[LL];           // g_j
__device__ float g_Pp[LL];          // p_{j+1} = C Ab^{j+1} h0
__device__ float g_Smat[QQ * NN];   // chunk forcing vectors
__device__ float g_hA[NN];
__device__ float g_hB[NN];
__device__ int   g_flag[1];         // 1 if h0 == 0 (skip W extension work)

// ---------------- flag: h0 all-zero? -------------------------------------------
__global__ void flag_kernel(const float* __restrict__ h0, int* __restrict__ flag) {
    __shared__ int any;
    if (threadIdx.x == 0) any = 0;
    __syncthreads();
    if (h0[threadIdx.x] != 0.0f) any = 1;   // benign race, all write 1
    __syncthreads();
    if (threadIdx.x == 0) *flag = any ? 0 : 1;
}

// ---------------- triangular solve: build Ab and Bb -----------------------------
// Solve (I - dt/2 A) Y = (I + dt/2 A)  column by column (A is lower triangular),
// plus one extra column for Bb: (I - dt/2 A) Bb = dt * B.
// One warp per column; 8 warps per block.
__global__ __launch_bounds__(256) void trisolve_kernel(
    const float* __restrict__ A, const float* __restrict__ B,
    float dt, float* __restrict__ Ab, float* __restrict__ Bb)
{
    __shared__ float ysh[8][NN];
    int wid  = threadIdx.x >> 5;
    int lane = threadIdx.x & 31;
    int j = blockIdx.x * 8 + wid;
    if (j > NN) return;
    float hdt = 0.5f * dt;
    float* y = ysh[wid];
    int i0 = (j < NN) ? j : 0;

    for (int i = i0; i < NN; ++i) {
        float s = 0.0f;
        const float* row = A + i * NN;
        for (int k = i0 + lane; k < i; k += 32) s += row[k] * y[k];
        #pragma unroll
        for (int off = 16; off; off >>= 1) s += __shfl_down_sync(0xffffffffu, s, off);
        if (lane == 0) {
            float rhs = (j < NN) ? ((i == j ? 1.0f : 0.0f) + hdt * row[j])
                                 : (dt * B[i]);
            y[i] = (rhs + hdt * s) / (1.0f - hdt * row[i]);
        }
        __syncwarp();
    }
    if (j < NN) {
        for (int i = lane; i < NN; i += 32)
            Ab[i * NN + j] = (i >= j) ? y[i] : 0.0f;
    } else {
        for (int i = lane; i < NN; i += 32) Bb[i] = y[i];
    }
}

// ---------------- seed: V[:,0] = Bb,  R row0 = C --------------------------------
__global__ void seed_kernel(const float* __restrict__ Bb, const float* __restrict__ C,
                            float* __restrict__ V, float* __restrict__ R)
{
    int t = blockIdx.x * blockDim.x + threadIdx.x;
    if (t < NN) { V[t * SS] = Bb[t]; R[t] = C[t]; }
}

// ---------------- generic matvec: out[r*ostride] = M[r,:].v + add[r] ------------
__global__ __launch_bounds__(256) void matvec_kernel(
    const float* __restrict__ M_, const float* __restrict__ v,
    const float* __restrict__ add, float* __restrict__ out, int ostride)
{
    int warp = (blockIdx.x * blockDim.x + threadIdx.x) >> 5;
    int lane = threadIdx.x & 31;
    if (warp >= NN) return;
    const float* row = M_ + warp * NN;
    float s = 0.0f;
    for (int k = lane; k < NN; k += 32) s += row[k] * v[k];
    #pragma unroll
    for (int off = 16; off; off >>= 1) s += __shfl_down_sync(0xffffffffu, s, off);
    if (lane == 0) out[warp * ostride] = s + (add ? add[warp] : 0.0f);
}

// ---------------- tiled fp32 GEMM: C = A(MxK) @ B(KxNd), row-major, ld params ---
static constexpr int BM = 64, BN = 64, BK = 16;
__global__ __launch_bounds__(256) void gemm_kernel(
    const float* __restrict__ A, const float* __restrict__ B, float* __restrict__ C,
    int M, int Nd, int K, int lda, int ldb, int ldc, const int* skip_flag)
{
    if (skip_flag && *skip_flag) return;
    __shared__ float As[BK][BM + 4];
    __shared__ float Bs[BK][BN];
    int tid = threadIdx.x;
    int tx = tid & 15;     // col group 0..15
    int ty = tid >> 4;     // row group 0..15
    int row0 = blockIdx.y * BM;
    int col0 = blockIdx.x * BN;
    float acc[4][4] = {};

    for (int k0 = 0; k0 < K; k0 += BK) {
        #pragma unroll
        for (int t = 0; t < 4; ++t) {                 // A tile 64x16
            int e = tid + 256 * t;
            int r = e >> 4, kk = e & 15;
            int gr = row0 + r, gk = k0 + kk;
            As[kk][r] = (gr < M && gk < K) ? A[gr * lda + gk] : 0.0f;
        }
        #pragma unroll
        for (int t = 0; t < 4; ++t) {                 // B tile 16x64
            int e = tid + 256 * t;
            int kk = e >> 6, c = e & 63;
            int gk = k0 + kk, gc = col0 + c;
            Bs[kk][c] = (gk < K && gc < Nd) ? B[gk * ldb + gc] : 0.0f;
        }
        __syncthreads();
        #pragma unroll
        for (int kk = 0; kk < BK; ++kk) {
            float a[4], b[4];
            #pragma unroll
            for (int i = 0; i < 4; ++i) a[i] = As[kk][ty * 4 + i];
            #pragma unroll
            for (int j = 0; j < 4; ++j) b[j] = Bs[kk][tx * 4 + j];
            #pragma unroll
            for (int i = 0; i < 4; ++i)
                #pragma unroll
                for (int j = 0; j < 4; ++j) acc[i][j] += a[i] * b[j];
        }
        __syncthreads();
    }
    #pragma unroll
    for (int i = 0; i < 4; ++i) {
        int gr = row0 + ty * 4 + i;
        if (gr >= M) continue;
        #pragma unroll
        for (int j = 0; j < 4; ++j) {
            int gc = col0 + tx * 4 + j;
            if (gc < Nd) C[gr * ldc + gc] = acc[i][j];
        }
    }
}

// ---------------- chunk forcing: Smat[q][i] = sum_b V[i][b] x[qS + S-1-b] -------
__global__ __launch_bounds__(256) void smat_kernel(
    const float* __restrict__ V, const float* __restrict__ x, float* __restrict__ Smat)
{
    int warp = (blockIdx.x * blockDim.x + threadIdx.x) >> 5;
    int lane = threadIdx.x & 31;
    if (warp >= QQ * NN) return;
    int q = warp >> 9;         // / 512
    int i = warp & (NN - 1);
    const float* vr = V + i * SS;
    const float* xr = x + q * SS;
    float s = 0.0f;
    for (int b = lane; b < SS; b += 32) s += vr[b] * xr[SS - 1 - b];
    #pragma unroll
    for (int off = 16; off; off >>= 1) s += __shfl_down_sync(0xffffffffu, s, off);
    if (lane == 0) Smat[q * NN + i] = s;
}

// ---------------- causal convolution: out[i] = Pp[i] + sum_{k<=i} g[i-k] x[k] ---
static constexpr int CT = 128;
__global__ __launch_bounds__(CT) void conv_kernel(
    const float* __restrict__ g, const float* __restrict__ x,
    const float* __restrict__ p, float* __restrict__ out)
{
    __shared__ float xs[CT];
    __shared__ float gs[2 * CT];
    int ti = threadIdx.x;
    int T0 = blockIdx.x * CT;
    int i = T0 + ti;
    float acc = 0.0f;

    for (int K0 = 0; K0 <= T0; K0 += CT) {
        int base = T0 - K0;
        xs[ti] = x[K0 + ti];
        #pragma unroll
        for (int t = 0; t < 2; ++t) {
            int j = ti + t * CT;
            if (j < 2 * CT - 1) {
                int gi = base - (CT - 1) + j;
                gs[j] = (gi >= 0) ? g[gi] : 0.0f;
            }
        }
        __syncthreads();
        int kmax = (K0 == T0) ? (ti + 1) : CT;
        int tk = 0;
        for (; tk + 4 <= kmax; tk += 4) {
            float x0 = xs[tk], x1 = xs[tk + 1], x2 = xs[tk + 2], x3 = xs[tk + 3];
            int b = CT - 1 + ti - tk;
            acc += gs[b] * x0 + gs[b - 1] * x1 + gs[b - 2] * x2 + gs[b - 3] * x3;
        }
        for (; tk < kmax; ++tk) acc += gs[CT - 1 + ti - tk] * xs[tk];
        __syncthreads();
    }
    out[i] = acc + p[i];
}

// ---------------- host ----------------------------------------------------------
static inline void gemm_launch(const float* A, const float* B, float* C,
                               int M, int Nd, int K, int lda, int ldb, int ldc,
                               const int* flag)
{
    dim3 grid((Nd + BN - 1) / BN, (M + BM - 1) / BM);
    gemm_kernel<<<grid, 256>>>(A, B, C, M, Nd, K, lda, ldb, ldc, flag);
}

extern "C" void kernel_launch(void* const* d_in, const int* in_sizes, int n_in,
                              void* d_out, int out_size)
{
    const float* x  = (const float*)d_in[0];  // (L,)
    const float* h0 = (const float*)d_in[1];  // (N,)
    const float* A  = (const float*)d_in[2];  // (N,N)
    const float* B  = (const float*)d_in[3];  // (N,1)
    const float* C  = (const float*)d_in[4];  // (1,N)
    float* out = (float*)d_out;

    float dt = 1.0f / (float)in_sizes[0];

    float *pAb, *pPa, *pPb, *pPc, *pBb, *pV, *pW, *pR, *pG, *pPp, *pSmat, *phA, *phB;
    int* pflag;
    cudaGetSymbolAddress((void**)&pAb,   g_Ab);
    cudaGetSymbolAddress((void**)&pPa,   g_Pa);
    cudaGetSymbolAddress((void**)&pPb,   g_Pb);
    cudaGetSymbolAddress((void**)&pPc,   g_Pc);
    cudaGetSymbolAddress((void**)&pBb,   g_Bb);
    cudaGetSymbolAddress((void**)&pV,    g_V);
    cudaGetSymbolAddress((void**)&pW,    g_W);
    cudaGetSymbolAddress((void**)&pR,    g_R);
    cudaGetSymbolAddress((void**)&pG,    g_G);
    cudaGetSymbolAddress((void**)&pPp,   g_Pp);
    cudaGetSymbolAddress((void**)&pSmat, g_Smat);
    cudaGetSymbolAddress((void**)&phA,   g_hA);
    cudaGetSymbolAddress((void**)&phB,   g_hB);
    cudaGetSymbolAddress((void**)&pflag, g_flag);

    // 1. h0 == 0 flag (skips the homogeneous-term GEMM work when zero)
    flag_kernel<<<1, NN>>>(h0, pflag);

    // 2. Build Ab, Bb by triangular solves (513 columns, warp each)
    trisolve_kernel<<<(NN + 1 + 7) / 8, 256>>>(A, B, dt, pAb, pBb);

    // 3. Seeds: V[:,0] = Bb, R[0] = C ; W[:,0] = Ab @ h0
    seed_kernel<<<2, 256>>>(pBb, C, pV, pR);
    matvec_kernel<<<64, 256>>>(pAb, h0, nullptr, pW, SS);

    // 4. Doubling chain: extend V (and W if h0 != 0), square powers.
    //    cur = Ab^m; after loop cur = Ab^1024.
    const float* cur = pAb;
    float* bufs[2] = { pPa, pPb };
    for (int step = 0; step < 10; ++step) {
        int m = 1 << step;
        // V[:, m..2m) = cur @ V[:, 0..m)
        gemm_launch(cur, pV, pV + m, NN, m, NN, NN, SS, SS, nullptr);
        // W[:, m..2m) = cur @ W[:, 0..m)   (skipped when h0 == 0)
        gemm_launch(cur, pW, pW + m, NN, m, NN, NN, SS, SS, pflag);
        // square
        float* nxt = bufs[step & 1];
        gemm_launch(cur, cur, nxt, NN, NN, NN, NN, NN, NN, nullptr);
        cur = nxt;
    }
    const float* PS = cur;   // Ab^1024  (lives in pPb; pPa now holds dead Ab^512)

    // 5. Rows c_{1024 q} = C Ab^{1024 q} by joint doubling:
    //    rows [m, 2m) = rows [0, m) @ PS^m, advancing PS^m by squaring.
    //    PS^1 = pPb (keep alive for step 8), PS^2 -> pPc, PS^4 -> pPa, PS^8 -> pPc.
    gemm_launch(pR, PS, pR + 1 * NN, 1, NN, NN, NN, NN, NN, nullptr);   // row 1
    gemm_launch(PS, PS, pPc, NN, NN, NN, NN, NN, NN, nullptr);          // PS^2
    gemm_launch(pR, pPc, pR + 2 * NN, 2, NN, NN, NN, NN, NN, nullptr);  // rows 2..3
    gemm_launch(pPc, pPc, pPa, NN, NN, NN, NN, NN, NN, nullptr);        // PS^4
    gemm_launch(pR, pPa, pR + 4 * NN, 4, NN, NN, NN, NN, NN, nullptr);  // rows 4..7
    gemm_launch(pPa, pPa, pPc, NN, NN, NN, NN, NN, NN, nullptr);        // PS^8
    gemm_launch(pR, pPc, pR + 8 * NN, 8, NN, NN, NN, NN, NN, nullptr);  // rows 8..15

    // 6. G = R @ V  (g_j),  Pp = R @ W  (p_{j+1})
    gemm_launch(pR, pV, pG,  QQ, SS, NN, NN, SS, SS, nullptr);
    gemm_launch(pR, pW, pPp, QQ, SS, NN, NN, SS, SS, nullptr);

    // 7. Chunk forcing vectors
    smat_kernel<<<(QQ * NN * 32 + 255) / 256, 256>>>(pV, x, pSmat);

    // 8. Final hidden state: h <- Ab^1024 h + s_q, 16 sequential matvecs
    bool write_h = (out_size >= LL + NN);
    const float* hsrc = h0;
    for (int q = 0; q < QQ; ++q) {
        float* hdst = (q == QQ - 1 && write_h) ? (out + LL)
                                               : ((q & 1) ? phB : phA);
        matvec_kernel<<<64, 256>>>(PS, hsrc, pSmat + q * NN, hdst, 1);
        hsrc = hdst;
    }

    // 9. Output convolution (+ homogeneous term)
    conv_kernel<<<LL / CT, CT>>>(pG, x, pPp, out);
}

// round 15
// speedup vs baseline: 1.2627x; 1.2627x over previous
#include <cuda_runtime.h>
#include <cuda_bf16.h>

// Linear state space layer, N=512, L=16384.
// y_i = sum_{k<=i} g_{i-k} x_k + C Ab^{i+1} h0,   g_j = C Ab^j Bb
// g_{1024q+b} = (C Ab^{1024q}) . (Ab^b Bb)
// h_L via bit-reversed binary-tree chunk scan with PS=Ab^1024 and PS^2,4,8.

static constexpr int NN = 512;     // state dim
static constexpr int SS = 1024;    // chunk size
static constexpr int QQ = 16;      // number of chunks
static constexpr int LL = 16384;   // sequence length

// ---------------- device scratch (zero-initialized at module load) -------------
__device__ float g_Ab[NN * NN];     // Ab (lower triangular)
__device__ float g_Pa[NN * NN];     // power ping   (ends: PS^8)
__device__ float g_Pb[NN * NN];     // power pong   (ends: PS = Ab^1024)
__device__ float g_Pc[NN * NN];     // PS^2
__device__ float g_Pd[NN * NN];     // PS^4
__device__ float g_Bb[NN];          // Bb
__device__ float g_V[NN * SS];      // columns v_b = Ab^b Bb   (row-major N x S)
__device__ float g_W[NN * SS];      // columns w'_b = Ab^{b+1} h0
__device__ float g_R[QQ * NN];      // rows c_{1024 q} = C Ab^{1024 q}
__device__ float g_G[LL];           // g_j  (as QQ x SS)
__device__ float g_Pp[LL];          // p_{j+1} = C Ab^{j+1} h0
__device__ float g_Smat[NN * QQ];   // chunk forcing vectors, N x 16, bit-rev cols
__device__ float g_T1[NN * 8];      // scan tree levels
__device__ float g_T2[NN * 4];
__device__ float g_T3[NN * 2];
__device__ float g_hA[NN];
__device__ int   g_flag[1];         // 1 if h0 == 0 (skip homogeneous-term work)

// ---------------- flag: h0 all-zero? -------------------------------------------
__global__ void flag_kernel(const float* __restrict__ h0, int* __restrict__ flag) {
    __shared__ int any;
    if (threadIdx.x == 0) any = 0;
    __syncthreads();
    if (h0[threadIdx.x] != 0.0f) any = 1;   // benign race, all write 1
    __syncthreads();
    if (threadIdx.x == 0) *flag = any ? 0 : 1;
}

// ---------------- triangular solve: build Ab and Bb -----------------------------
__global__ __launch_bounds__(256) void trisolve_kernel(
    const float* __restrict__ A, const float* __restrict__ B,
    float dt, float* __restrict__ Ab, float* __restrict__ Bb)
{
    __shared__ float ysh[8][NN];
    int wid  = threadIdx.x >> 5;
    int lane = threadIdx.x & 31;
    int j = blockIdx.x * 8 + wid;
    if (j > NN) return;
    float hdt = 0.5f * dt;
    float* y = ysh[wid];
    int i0 = (j < NN) ? j : 0;

    for (int i = i0; i < NN; ++i) {
        float s = 0.0f;
        const float* row = A + i * NN;
        for (int k = i0 + lane; k < i; k += 32) s += row[k] * y[k];
        #pragma unroll
        for (int off = 16; off; off >>= 1) s += __shfl_down_sync(0xffffffffu, s, off);
        if (lane == 0) {
            float rhs = (j < NN) ? ((i == j ? 1.0f : 0.0f) + hdt * row[j])
                                 : (dt * B[i]);
            y[i] = (rhs + hdt * s) / (1.0f - hdt * row[i]);
        }
        __syncwarp();
    }
    if (j < NN) {
        for (int i = lane; i < NN; i += 32)
            Ab[i * NN + j] = (i >= j) ? y[i] : 0.0f;
    } else {
        for (int i = lane; i < NN; i += 32) Bb[i] = y[i];
    }
}

// ---------------- seed: V[:,0] = Bb,  R row0 = C --------------------------------
__global__ void seed_kernel(const float* __restrict__ Bb, const float* __restrict__ C,
                            float* __restrict__ V, float* __restrict__ R)
{
    int t = blockIdx.x * blockDim.x + threadIdx.x;
    if (t < NN) { V[t * SS] = Bb[t]; R[t] = C[t]; }
}

// ---------------- matvec: out[r*ostride] = M.v + add[r*astride], flag-skippable -
__global__ __launch_bounds__(256) void matvec_kernel(
    const float* __restrict__ M_, const float* __restrict__ v,
    const float* __restrict__ add, float* __restrict__ out,
    int ostride, int astride, const int* skip_flag)
{
    if (skip_flag && *skip_flag) return;
    int warp = (blockIdx.x * blockDim.x + threadIdx.x) >> 5;
    int lane = threadIdx.x & 31;
    if (warp >= NN) return;
    const float* row = M_ + warp * NN;
    float s = 0.0f;
    #pragma unroll 4
    for (int k = lane; k < NN; k += 32) s += row[k] * v[k];
    #pragma unroll
    for (int off = 16; off; off >>= 1) s += __shfl_down_sync(0xffffffffu, s, off);
    if (lane == 0) out[warp * ostride] = s + (add ? add[warp * astride] : 0.0f);
}

// ---------------- grouped tiled fp32 GEMM --------------------------------------
// Each segment: C = A(MxK) @ B(KxNd) [+ D], row-major with explicit ld's.
static constexpr int BM = 64, BN = 64, BK = 16;

struct Seg {
    const float* A; const float* B; const float* D; float* C;
    int M, Nd, K, lda, ldb, ldd, ldc;
    const int* flag;      // skip segment when *flag != 0
};

__device__ __forceinline__ void gemm_tile(const Seg s, int bx, int by)
{
    if (s.flag && *s.flag) return;
    int row0 = by * BM;
    if (row0 >= s.M) return;
    int col0 = bx * BN;

    __shared__ float As[BK][BM + 4];
    __shared__ float Bs[BK][BN];
    int tid = threadIdx.x;
    int tx = tid & 15;
    int ty = tid >> 4;
    float acc[4][4] = {};

    for (int k0 = 0; k0 < s.K; k0 += BK) {
        #pragma unroll
        for (int t = 0; t < 4; ++t) {                 // A tile 64x16
            int e = tid + 256 * t;
            int r = e >> 4, kk = e & 15;
            int gr = row0 + r, gk = k0 + kk;
            As[kk][r] = (gr < s.M && gk < s.K) ? s.A[gr * s.lda + gk] : 0.0f;
        }
        #pragma unroll
        for (int t = 0; t < 4; ++t) {                 // B tile 16x64
            int e = tid + 256 * t;
            int kk = e >> 6, c = e & 63;
            int gk = k0 + kk, gc = col0 + c;
            Bs[kk][c] = (gk < s.K && gc < s.Nd) ? s.B[gk * s.ldb + gc] : 0.0f;
        }
        __syncthreads();
        #pragma unroll
        for (int kk = 0; kk < BK; ++kk) {
            float a[4], b[4];
            #pragma unroll
            for (int i = 0; i < 4; ++i) a[i] = As[kk][ty * 4 + i];
            #pragma unroll
            for (int j = 0; j < 4; ++j) b[j] = Bs[kk][tx * 4 + j];
            #pragma unroll
            for (int i = 0; i < 4; ++i)
                #pragma unroll
                for (int j = 0; j < 4; ++j) acc[i][j] += a[i] * b[j];
        }
        __syncthreads();
    }
    #pragma unroll
    for (int i = 0; i < 4; ++i) {
        int gr = row0 + ty * 4 + i;
        if (gr >= s.M) continue;
        #pragma unroll
        for (int j = 0; j < 4; ++j) {
            int gc = col0 + tx * 4 + j;
            if (gc < s.Nd)
                s.C[gr * s.ldc + gc] = acc[i][j] + (s.D ? s.D[gr * s.ldd + gc] : 0.0f);
        }
    }
}

__global__ __launch_bounds__(256) void gemm1_kernel(Seg s0) {
    gemm_tile(s0, blockIdx.x, blockIdx.y);
}
__global__ __launch_bounds__(256) void gemm2_kernel(Seg s0, Seg s1, int t0) {
    int bx = blockIdx.x;
    if (bx < t0) gemm_tile(s0, bx, blockIdx.y);
    else         gemm_tile(s1, bx - t0, blockIdx.y);
}
__global__ __launch_bounds__(256) void gemm3_kernel(Seg s0, Seg s1, Seg s2, int t0, int t01) {
    int bx = blockIdx.x;
    if (bx < t0)       gemm_tile(s0, bx, blockIdx.y);
    else if (bx < t01) gemm_tile(s1, bx - t0, blockIdx.y);
    else               gemm_tile(s2, bx - t01, blockIdx.y);
}

// ---------------- chunk forcing: Smat[i][brev(q)] = sum_b V[i][b] x[qS+S-1-b] ---
__global__ __launch_bounds__(256) void smat_kernel(
    const float* __restrict__ V, const float* __restrict__ x, float* __restrict__ Smat)
{
    int warp = (blockIdx.x * blockDim.x + threadIdx.x) >> 5;
    int lane = threadIdx.x & 31;
    if (warp >= QQ * NN) return;
    int q = warp >> 9;         // / 512
    int i = warp & (NN - 1);
    const float* vr = V + i * SS;
    const float* xr = x + q * SS;
    float s = 0.0f;
    for (int b = lane; b < SS; b += 32) s += vr[b] * xr[SS - 1 - b];
    #pragma unroll
    for (int off = 16; off; off >>= 1) s += __shfl_down_sync(0xffffffffu, s, off);
    int p = ((q & 1) << 3) | ((q & 2) << 1) | ((q & 4) >> 1) | ((q & 8) >> 3); // bitrev4
    if (lane == 0) Smat[i * QQ + p] = s;
}

// ---------------- causal convolution: out[i] = Pp[i] + sum_{k<=i} g[i-k] x[k] ---
static constexpr int CT = 128;
__global__ __launch_bounds__(CT) void conv_kernel(
    const float* __restrict__ g, const float* __restrict__ x,
    const float* __restrict__ p, float* __restrict__ out)
{
    __shared__ float xs[CT];
    __shared__ float gs[2 * CT];
    int ti = threadIdx.x;
    int T0 = blockIdx.x * CT;
    int i = T0 + ti;
    float acc = 0.0f;

    for (int K0 = 0; K0 <= T0; K0 += CT) {
        int base = T0 - K0;
        xs[ti] = x[K0 + ti];
        #pragma unroll
        for (int t = 0; t < 2; ++t) {
            int j = ti + t * CT;
            if (j < 2 * CT - 1) {
                int gi = base - (CT - 1) + j;
                gs[j] = (gi >= 0) ? g[gi] : 0.0f;
            }
        }
        __syncthreads();
        int kmax = (K0 == T0) ? (ti + 1) : CT;
        int tk = 0;
        for (; tk + 4 <= kmax; tk += 4) {
            float x0 = xs[tk], x1 = xs[tk + 1], x2 = xs[tk + 2], x3 = xs[tk + 3];
            int b = CT - 1 + ti - tk;
            acc += gs[b] * x0 + gs[b - 1] * x1 + gs[b - 2] * x2 + gs[b - 3] * x3;
        }
        for (; tk < kmax; ++tk) acc += gs[CT - 1 + ti - tk] * xs[tk];
        __syncthreads();
    }
    out[i] = acc + p[i];
}

// ---------------- host ----------------------------------------------------------
static inline Seg mkseg(const float* A, const float* B, const float* D, float* C,
                        int M, int Nd, int K, int lda, int ldb, int ldd, int ldc,
                        const int* flag)
{
    Seg s; s.A = A; s.B = B; s.D = D; s.C = C;
    s.M = M; s.Nd = Nd; s.K = K; s.lda = lda; s.ldb = ldb; s.ldd = ldd; s.ldc = ldc;
    s.flag = flag; return s;
}
static inline int tiles_n(int n) { return (n + BN - 1) / BN; }
static inline int tiles_m(int m) { return (m + BM - 1) / BM; }

extern "C" void kernel_launch(void* const* d_in, const int* in_sizes, int n_in,
                              void* d_out, int out_size)
{
    const float* x  = (const float*)d_in[0];  // (L,)
    const float* h0 = (const float*)d_in[1];  // (N,)
    const float* A  = (const float*)d_in[2];  // (N,N)
    const float* B  = (const float*)d_in[3];  // (N,1)
    const float* C  = (const float*)d_in[4];  // (1,N)
    float* out = (float*)d_out;

    float dt = 1.0f / (float)in_sizes[0];

    float *pAb, *pPa, *pPb, *pPc, *pPd, *pBb, *pV, *pW, *pR, *pG, *pPp;
    float *pSmat, *pT1, *pT2, *pT3, *phA;
    int* pflag;
    cudaGetSymbolAddress((void**)&pAb,   g_Ab);
    cudaGetSymbolAddress((void**)&pPa,   g_Pa);
    cudaGetSymbolAddress((void**)&pPb,   g_Pb);
    cudaGetSymbolAddress((void**)&pPc,   g_Pc);
    cudaGetSymbolAddress((void**)&pPd,   g_Pd);
    cudaGetSymbolAddress((void**)&pBb,   g_Bb);
    cudaGetSymbolAddress((void**)&pV,    g_V);
    cudaGetSymbolAddress((void**)&pW,    g_W);
    cudaGetSymbolAddress((void**)&pR,    g_R);
    cudaGetSymbolAddress((void**)&pG,    g_G);
    cudaGetSymbolAddress((void**)&pPp,   g_Pp);
    cudaGetSymbolAddress((void**)&pSmat, g_Smat);
    cudaGetSymbolAddress((void**)&pT1,   g_T1);
    cudaGetSymbolAddress((void**)&pT2,   g_T2);
    cudaGetSymbolAddress((void**)&pT3,   g_T3);
    cudaGetSymbolAddress((void**)&phA,   g_hA);
    cudaGetSymbolAddress((void**)&pflag, g_flag);

    // 1. h0 == 0 flag
    flag_kernel<<<1, NN>>>(h0, pflag);

    // 2. Build Ab, Bb (513 triangular solves)
    trisolve_kernel<<<(NN + 1 + 7) / 8, 256>>>(A, B, dt, pAb, pBb);

    // 3. Seeds: V[:,0] = Bb, R[0] = C ; W[:,0] = Ab @ h0 (skip if h0 == 0)
    seed_kernel<<<2, 256>>>(pBb, C, pV, pR);
    matvec_kernel<<<64, 256>>>(pAb, h0, nullptr, pW, SS, 1, pflag);

    // 4. Doubling chain, fused per step: {V-ext, W-ext(flag), square} one launch.
    //    cur = Ab^m; after loop PS = Ab^1024 in pPb (pPa = dead Ab^512).
    const float* cur = pAb;
    float* bufs[2] = { pPa, pPb };
    for (int step = 0; step < 10; ++step) {
        int m = 1 << step;
        float* nxt = bufs[step & 1];
        Seg sv = mkseg(cur, pV, nullptr, pV + m, NN, m, NN, NN, SS, 0, SS, nullptr);
        Seg sw = mkseg(cur, pW, nullptr, pW + m, NN, m, NN, NN, SS, 0, SS, pflag);
        Seg sq = mkseg(cur, cur, nullptr, nxt,   NN, NN, NN, NN, NN, 0, NN, nullptr);
        int tv = tiles_n(m);
        dim3 grid(2 * tv + tiles_n(NN), tiles_m(NN));
        gemm3_kernel<<<grid, 256>>>(sv, sw, sq, tv, 2 * tv);
        cur = nxt;
    }
    const float* PS = cur;   // Ab^1024 in pPb

    // 5. Chunk forcing vectors (bit-reversed columns) — only needs V and x
    smat_kernel<<<(QQ * NN * 32 + 255) / 256, 256>>>(pV, x, pSmat);

    // 6. Rows c_{1024 q} = C Ab^{1024 q} by joint doubling, fused with the
    //    PS^m squarings (needed later by the scan tree):
    //    PS^2 -> pPc, PS^4 -> pPd, PS^8 -> pPa (Ab^512 is dead).
    {
        Seg r1 = mkseg(pR, PS,  nullptr, pR + 1 * NN, 1, NN, NN, NN, NN, 0, NN, nullptr);
        Seg q1 = mkseg(PS, PS,  nullptr, pPc,         NN, NN, NN, NN, NN, 0, NN, nullptr);
        gemm2_kernel<<<dim3(16, 8), 256>>>(r1, q1, 8);

        Seg r2 = mkseg(pR, pPc, nullptr, pR + 2 * NN, 2, NN, NN, NN, NN, 0, NN, nullptr);
        Seg q2 = mkseg(pPc, pPc, nullptr, pPd,        NN, NN, NN, NN, NN, 0, NN, nullptr);
        gemm2_kernel<<<dim3(16, 8), 256>>>(r2, q2, 8);

        Seg r4 = mkseg(pR, pPd, nullptr, pR + 4 * NN, 4, NN, NN, NN, NN, 0, NN, nullptr);
        Seg q4 = mkseg(pPd, pPd, nullptr, pPa,        NN, NN, NN, NN, NN, 0, NN, nullptr);
        gemm2_kernel<<<dim3(16, 8), 256>>>(r4, q4, 8);

        Seg r8 = mkseg(pR, pPa, nullptr, pR + 8 * NN, 8, NN, NN, NN, NN, 0, NN, nullptr);
        gemm1_kernel<<<dim3(8, 1), 256>>>(r8);
    }

    // 7. G = R @ V  and  Pp = R @ W (flag-guarded), one launch
    {
        Seg sg = mkseg(pR, pV, nullptr, pG,  QQ, SS, NN, NN, SS, 0, SS, nullptr);
        Seg sp = mkseg(pR, pW, nullptr, pPp, QQ, SS, NN, NN, SS, 0, SS, pflag);
        gemm2_kernel<<<dim3(32, 1), 256>>>(sg, sp, 16);
    }

    // 8. Fold h0 into the scan: s_0 <- s_0 + PS @ h0 (skip if h0 == 0).
    //    s_0 lives at bit-reversed column 0 of Smat, stride QQ.
    matvec_kernel<<<64, 256>>>(PS, h0, pSmat, pSmat, QQ, QQ, pflag);

    // 9. Binary-tree chunk scan: h_L = sum_q PS^{15-q} s_q  (+ PS^16 h0 via fold)
    //    Level w: OUT(N x w) = PS^{16/(2w)} @ IN[:,0:w] + IN[:,w:2w]
    bool write_h = (out_size >= LL + NN);
    float* hdst = write_h ? (out + LL) : phA;
    {
        Seg l1 = mkseg(pPb, pSmat,     pSmat + 8, pT1, NN, 8, NN, NN, QQ, QQ, 8, nullptr);
        gemm1_kernel<<<dim3(1, 8), 256>>>(l1);
        Seg l2 = mkseg(pPc, pT1,       pT1 + 4,   pT2, NN, 4, NN, NN, 8,  8,  4, nullptr);
        gemm1_kernel<<<dim3(1, 8), 256>>>(l2);
        Seg l3 = mkseg(pPd, pT2,       pT2 + 2,   pT3, NN, 2, NN, NN, 4,  4,  2, nullptr);
        gemm1_kernel<<<dim3(1, 8), 256>>>(l3);
        Seg l4 = mkseg(pPa, pT3,       pT3 + 1,   hdst, NN, 1, NN, NN, 2,  2,  1, nullptr);
        gemm1_kernel<<<dim3(1, 8), 256>>>(l4);
    }

    // 10. Output convolution (+ homogeneous term)
    conv_kernel<<<LL / CT, CT>>>(pG, x, pPp, out);
}

// round 17
// speedup vs baseline: 1.6382x; 1.2974x over previous
#include <cuda_runtime.h>
#include <cuda_bf16.h>

// Linear state space layer, N=512, L=16384.
// y_i = sum_{k<=i} g_{i-k} x_k + C Ab^{i+1} h0,   g_j = C Ab^j Bb
// g_{1024q+b} = (C Ab^{1024q}) . (Ab^b Bb)
// h_L via bit-reversed binary-tree chunk scan with PS=Ab^1024 and PS^2,4,8.
// All powers of Ab are LOWER TRIANGULAR -> tile skipping + shortened K ranges.

static constexpr int NN = 512;     // state dim
static constexpr int SS = 1024;    // chunk size
static constexpr int QQ = 16;      // number of chunks
static constexpr int LL = 16384;   // sequence length

// ---------------- device scratch (zero-initialized at module load) -------------
// Upper triangles of Ab/Pa/Pb/Pc/Pd are NEVER written (zero-init invariant).
__device__ float g_Ab[NN * NN];     // Ab (lower triangular)
__device__ float g_Pa[NN * NN];     // power ping   (ends: PS^8)
__device__ float g_Pb[NN * NN];     // power pong   (ends: PS = Ab^1024)
__device__ float g_Pc[NN * NN];     // PS^2
__device__ float g_Pd[NN * NN];     // PS^4
__device__ float g_Bb[NN];          // Bb
__device__ float g_V[NN * SS];      // columns v_b = Ab^b Bb   (row-major N x S)
__device__ float g_W[NN * SS];      // columns w'_b = Ab^{b+1} h0
__device__ float g_R[QQ * NN];      // rows c_{1024 q} = C Ab^{1024 q}
__device__ float g_G[LL];           // g_j  (as QQ x SS)
__device__ float g_Pp[LL];          // p_{j+1} = C Ab^{j+1} h0 (zero if h0==0)
__device__ float g_Smat[NN * QQ];   // chunk forcing vectors, N x 16, bit-rev cols
__device__ float g_T1[NN * 8];      // scan tree levels
__device__ float g_T2[NN * 4];
__device__ float g_T3[NN * 2];
__device__ float g_hA[NN];
__device__ float g_CP[4 * LL];      // conv k-slice partials
__device__ int   g_flag[1];         // 1 if h0 == 0 (skip homogeneous-term work)

// ---------------- flag: h0 all-zero? -------------------------------------------
__global__ void flag_kernel(const float* __restrict__ h0, int* __restrict__ flag) {
    __shared__ int any;
    if (threadIdx.x == 0) any = 0;
    __syncthreads();
    if (h0[threadIdx.x] != 0.0f) any = 1;   // benign race, all write 1
    __syncthreads();
    if (threadIdx.x == 0) *flag = any ? 0 : 1;
}

// ---------------- triangular solve: build Ab and Bb -----------------------------
__global__ __launch_bounds__(256) void trisolve_kernel(
    const float* __restrict__ A, const float* __restrict__ B,
    float dt, float* __restrict__ Ab, float* __restrict__ Bb)
{
    __shared__ float ysh[8][NN];
    int wid  = threadIdx.x >> 5;
    int lane = threadIdx.x & 31;
    int j = blockIdx.x * 8 + wid;
    if (j > NN) return;
    float hdt = 0.5f * dt;
    float* y = ysh[wid];
    int i0 = (j < NN) ? j : 0;

    for (int i = i0; i < NN; ++i) {
        float s = 0.0f;
        const float* row = A + i * NN;
        for (int k = i0 + lane; k < i; k += 32) s += row[k] * y[k];
        #pragma unroll
        for (int off = 16; off; off >>= 1) s += __shfl_down_sync(0xffffffffu, s, off);
        if (lane == 0) {
            float rhs = (j < NN) ? ((i == j ? 1.0f : 0.0f) + hdt * row[j])
                                 : (dt * B[i]);
            y[i] = (rhs + hdt * s) / (1.0f - hdt * row[i]);
        }
        __syncwarp();
    }
    if (j < NN) {
        // write only lower triangle (upper stays zero from static init)
        for (int i = j + (lane - (j & 31) + 32) % 32; i < NN; i += 32)
            Ab[i * NN + j] = y[i];
        // note: loop above starts at first index >= j congruent to lane
    } else {
        for (int i = lane; i < NN; i += 32) Bb[i] = y[i];
    }
}

// ---------------- seed: V[:,0] = Bb,  R row0 = C --------------------------------
__global__ void seed_kernel(const float* __restrict__ Bb, const float* __restrict__ C,
                            float* __restrict__ V, float* __restrict__ R)
{
    int t = blockIdx.x * blockDim.x + threadIdx.x;
    if (t < NN) { V[t * SS] = Bb[t]; R[t] = C[t]; }
}

// ---------------- matvec: out[r*ostride] = M.v + add[r*astride], flag-skippable -
__global__ __launch_bounds__(256) void matvec_kernel(
    const float* __restrict__ M_, const float* __restrict__ v,
    const float* __restrict__ add, float* __restrict__ out,
    int ostride, int astride, const int* skip_flag)
{
    if (skip_flag && *skip_flag) return;
    int warp = (blockIdx.x * blockDim.x + threadIdx.x) >> 5;
    int lane = threadIdx.x & 31;
    if (warp >= NN) return;
    const float* row = M_ + warp * NN;
    float s = 0.0f;
    #pragma unroll 4
    for (int k = lane; k < NN; k += 32) s += row[k] * v[k];
    #pragma unroll
    for (int off = 16; off; off >>= 1) s += __shfl_down_sync(0xffffffffu, s, off);
    if (lane == 0) out[warp * ostride] = s + (add ? add[warp * astride] : 0.0f);
}

// ---------------- grouped tiled fp32 GEMM, triangular-aware --------------------
// Each segment: C = A(MxK) @ B(KxNd) [+ D], row-major with explicit ld's.
// alow: A lower-triangular -> k < row0+BM.  blow: B lower-triangular -> k >= col0.
// alow&&blow -> strictly-upper output tiles skipped (left untouched = zero).
static constexpr int BM = 32, BN = 64, BK = 16;

struct Seg {
    const float* A; const float* B; const float* D; float* C;
    int M, Nd, K, lda, ldb, ldd, ldc;
    int alow, blow;
    const int* flag;      // skip segment when *flag != 0
};

__device__ __forceinline__ void gemm_tile(const Seg s, int bx, int by)
{
    if (s.flag && *s.flag) return;
    int row0 = by * BM;
    if (row0 >= s.M) return;
    int col0 = bx * BN;
    if (s.alow && s.blow && col0 >= row0 + BM) return;   // zero tile: skip, don't write

    int k_lo = s.blow ? col0 : 0;
    int k_hi = s.alow ? ((row0 + BM < s.K) ? row0 + BM : s.K) : s.K;

    __shared__ float As[BK][BM + 2];   // +2: 8B-aligned rows, conflict-free stores
    __shared__ float Bs[BK][BN];
    int tid = threadIdx.x;
    int tx = tid & 15;     // 16 col groups * 4
    int ty = tid >> 4;     // 16 row groups * 2
    float acc[2][4] = {};

    for (int k0 = k_lo; k0 < k_hi; k0 += BK) {
        {   // A tile 32x16, 2 elems/thread, coalesced on k
            #pragma unroll
            for (int t = 0; t < 2; ++t) {
                int e = tid + 256 * t;
                int r = e >> 4, kk = e & 15;
                int gr = row0 + r, gk = k0 + kk;
                As[kk][r] = (gr < s.M && gk < s.K) ? s.A[gr * s.lda + gk] : 0.0f;
            }
        }
        {   // B tile 16x64, 4 elems/thread, coalesced on columns
            #pragma unroll
            for (int t = 0; t < 4; ++t) {
                int e = tid + 256 * t;
                int kk = e >> 6, c = e & 63;
                int gk = k0 + kk, gc = col0 + c;
                Bs[kk][c] = (gk < s.K && gc < s.Nd) ? s.B[gk * s.ldb + gc] : 0.0f;
            }
        }
        __syncthreads();
        #pragma unroll
        for (int kk = 0; kk < BK; ++kk) {
            float a0 = As[kk][ty * 2];
            float a1 = As[kk][ty * 2 + 1];
            float b0 = Bs[kk][tx * 4 + 0];
            float b1 = Bs[kk][tx * 4 + 1];
            float b2 = Bs[kk][tx * 4 + 2];
            float b3 = Bs[kk][tx * 4 + 3];
            acc[0][0] += a0 * b0; acc[0][1] += a0 * b1;
            acc[0][2] += a0 * b2; acc[0][3] += a0 * b3;
            acc[1][0] += a1 * b0; acc[1][1] += a1 * b1;
            acc[1][2] += a1 * b2; acc[1][3] += a1 * b3;
        }
        __syncthreads();
    }
    #pragma unroll
    for (int i = 0; i < 2; ++i) {
        int gr = row0 + ty * 2 + i;
        if (gr >= s.M) continue;
        #pragma unroll
        for (int j = 0; j < 4; ++j) {
            int gc = col0 + tx * 4 + j;
            if (gc < s.Nd)
                s.C[gr * s.ldc + gc] = acc[i][j] + (s.D ? s.D[gr * s.ldd + gc] : 0.0f);
        }
    }
}

__global__ __launch_bounds__(256) void gemm1_kernel(Seg s0) {
    gemm_tile(s0, blockIdx.x, blockIdx.y);
}
__global__ __launch_bounds__(256) void gemm2_kernel(Seg s0, Seg s1, int t0) {
    int bx = blockIdx.x;
    if (bx < t0) gemm_tile(s0, bx, blockIdx.y);
    else         gemm_tile(s1, bx - t0, blockIdx.y);
}
__global__ __launch_bounds__(256) void gemm3_kernel(Seg s0, Seg s1, Seg s2, int t0, int t01) {
    int bx = blockIdx.x;
    if (bx < t0)       gemm_tile(s0, bx, blockIdx.y);
    else if (bx < t01) gemm_tile(s1, bx - t0, blockIdx.y);
    else               gemm_tile(s2, bx - t01, blockIdx.y);
}

// ---------------- chunk forcing: Smat[i][brev(q)] = sum_b V[i][b] x[qS+S-1-b] ---
__global__ __launch_bounds__(256) void smat_kernel(
    const float* __restrict__ V, const float* __restrict__ x, float* __restrict__ Smat)
{
    int warp = (blockIdx.x * blockDim.x + threadIdx.x) >> 5;
    int lane = threadIdx.x & 31;
    if (warp >= QQ * NN) return;
    int q = warp >> 9;         // / 512
    int i = warp & (NN - 1);
    const float* vr = V + i * SS;
    const float* xr = x + q * SS;
    float s = 0.0f;
    for (int b = lane; b < SS; b += 32) s += vr[b] * xr[SS - 1 - b];
    #pragma unroll
    for (int off = 16; off; off >>= 1) s += __shfl_down_sync(0xffffffffu, s, off);
    int p = ((q & 1) << 3) | ((q & 2) << 1) | ((q & 4) >> 1) | ((q & 8) >> 3); // bitrev4
    if (lane == 0) Smat[i * QQ + p] = s;
}

// ---------------- causal convolution, k-sliced partials -------------------------
// Block (ib, s): outputs [ib*CT, ib*CT+CT), k-chunks slice s of ib+1 chunks.
// Partial sums to g_CP (always written -> deterministic), combined later.
static constexpr int CT = 128;
__global__ __launch_bounds__(CT) void conv_part_kernel(
    const float* __restrict__ g, const float* __restrict__ x, float* __restrict__ CP)
{
    __shared__ float xs[CT];
    __shared__ float gs[2 * CT];
    int ti = threadIdx.x;
    int ib = blockIdx.x;
    int sl = blockIdx.y;
    int T0 = ib * CT;
    int i = T0 + ti;
    int nch = ib + 1;
    int c0 = (sl * nch) >> 2;
    int c1 = ((sl + 1) * nch) >> 2;
    float acc = 0.0f;

    for (int c = c0; c < c1; ++c) {
        int K0 = c * CT;
        int base = T0 - K0;
        xs[ti] = x[K0 + ti];
        #pragma unroll
        for (int t = 0; t < 2; ++t) {
            int j = ti + t * CT;
            if (j < 2 * CT - 1) {
                int gi = base - (CT - 1) + j;
                gs[j] = (gi >= 0) ? g[gi] : 0.0f;
            }
        }
        __syncthreads();
        int kmax = (c == ib) ? (ti + 1) : CT;
        int tk = 0;
        for (; tk + 4 <= kmax; tk += 4) {
            float x0 = xs[tk], x1 = xs[tk + 1], x2 = xs[tk + 2], x3 = xs[tk + 3];
            int b = CT - 1 + ti - tk;
            acc += gs[b] * x0 + gs[b - 1] * x1 + gs[b - 2] * x2 + gs[b - 3] * x3;
        }
        for (; tk < kmax; ++tk) acc += gs[CT - 1 + ti - tk] * xs[tk];
        __syncthreads();
    }
    CP[sl * LL + i] = acc;
}

__global__ __launch_bounds__(256) void conv_combine_kernel(
    const float* __restrict__ CP, const float* __restrict__ p, float* __restrict__ out)
{
    int i = blockIdx.x * blockDim.x + threadIdx.x;
    out[i] = p[i] + CP[i] + CP[LL + i] + CP[2 * LL + i] + CP[3 * LL + i];
}

// ---------------- host ----------------------------------------------------------
static inline Seg mkseg(const float* A, const float* B, const float* D, float* C,
                        int M, int Nd, int K, int lda, int ldb, int ldd, int ldc,
                        int alow, int blow, const int* flag)
{
    Seg s; s.A = A; s.B = B; s.D = D; s.C = C;
    s.M = M; s.Nd = Nd; s.K = K; s.lda = lda; s.ldb = ldb; s.ldd = ldd; s.ldc = ldc;
    s.alow = alow; s.blow = blow; s.flag = flag; return s;
}
static inline int tiles_n(int n) { return (n + BN - 1) / BN; }
static inline int tiles_m(int m) { return (m + BM - 1) / BM; }

extern "C" void kernel_launch(void* const* d_in, const int* in_sizes, int n_in,
                              void* d_out, int out_size)
{
    const float* x  = (const float*)d_in[0];  // (L,)
    const float* h0 = (const float*)d_in[1];  // (N,)
    const float* A  = (const float*)d_in[2];  // (N,N)
    const float* B  = (const float*)d_in[3];  // (N,1)
    const float* C  = (const float*)d_in[4];  // (1,N)
    float* out = (float*)d_out;

    float dt = 1.0f / (float)in_sizes[0];

    float *pAb, *pPa, *pPb, *pPc, *pPd, *pBb, *pV, *pW, *pR, *pG, *pPp;
    float *pSmat, *pT1, *pT2, *pT3, *phA, *pCP;
    int* pflag;
    cudaGetSymbolAddress((void**)&pAb,   g_Ab);
    cudaGetSymbolAddress((void**)&pPa,   g_Pa);
    cudaGetSymbolAddress((void**)&pPb,   g_Pb);
    cudaGetSymbolAddress((void**)&pPc,   g_Pc);
    cudaGetSymbolAddress((void**)&pPd,   g_Pd);
    cudaGetSymbolAddress((void**)&pBb,   g_Bb);
    cudaGetSymbolAddress((void**)&pV,    g_V);
    cudaGetSymbolAddress((void**)&pW,    g_W);
    cudaGetSymbolAddress((void**)&pR,    g_R);
    cudaGetSymbolAddress((void**)&pG,    g_G);
    cudaGetSymbolAddress((void**)&pPp,   g_Pp);
    cudaGetSymbolAddress((void**)&pSmat, g_Smat);
    cudaGetSymbolAddress((void**)&pT1,   g_T1);
    cudaGetSymbolAddress((void**)&pT2,   g_T2);
    cudaGetSymbolAddress((void**)&pT3,   g_T3);
    cudaGetSymbolAddress((void**)&phA,   g_hA);
    cudaGetSymbolAddress((void**)&pCP,   g_CP);
    cudaGetSymbolAddress((void**)&pflag, g_flag);

    // 1. h0 == 0 flag
    flag_kernel<<<1, NN>>>(h0, pflag);

    // 2. Build Ab (lower triangle only), Bb
    trisolve_kernel<<<(NN + 1 + 7) / 8, 256>>>(A, B, dt, pAb, pBb);

    // 3. Seeds: V[:,0] = Bb, R[0] = C ; W[:,0] = Ab @ h0 (skip if h0 == 0)
    seed_kernel<<<2, 256>>>(pBb, C, pV, pR);
    matvec_kernel<<<64, 256>>>(pAb, h0, nullptr, pW, SS, 1, pflag);

    // 4. Doubling chain, fused per step: {V-ext, W-ext(flag), square} one launch.
    //    All operands triangular where flagged; upper output tiles untouched.
    const float* cur = pAb;
    float* bufs[2] = { pPa, pPb };
    for (int step = 0; step < 10; ++step) {
        int m = 1 << step;
        float* nxt = bufs[step & 1];
        Seg sv = mkseg(cur, pV, nullptr, pV + m, NN, m, NN, NN, SS, 0, SS, 1, 0, nullptr);
        Seg sw = mkseg(cur, pW, nullptr, pW + m, NN, m, NN, NN, SS, 0, SS, 1, 0, pflag);
        Seg sq = mkseg(cur, cur, nullptr, nxt,   NN, NN, NN, NN, NN, 0, NN, 1, 1, nullptr);
        int tv = tiles_n(m);
        dim3 grid(2 * tv + tiles_n(NN), tiles_m(NN));
        gemm3_kernel<<<grid, 256>>>(sv, sw, sq, tv, 2 * tv);
        cur = nxt;
    }
    const float* PS = cur;   // Ab^1024 in pPb

    // 5. Chunk forcing vectors (bit-reversed columns)
    smat_kernel<<<(QQ * NN * 32 + 255) / 256, 256>>>(pV, x, pSmat);

    // 6. Rows c_{1024 q} = C Ab^{1024 q} by joint doubling, fused with the
    //    PS^m squarings (needed by the scan tree): PS^2->pPc, PS^4->pPd, PS^8->pPa.
    {
        Seg r1 = mkseg(pR, PS,  nullptr, pR + 1 * NN, 1, NN, NN, NN, NN, 0, NN, 0, 1, nullptr);
        Seg q1 = mkseg(PS, PS,  nullptr, pPc,         NN, NN, NN, NN, NN, 0, NN, 1, 1, nullptr);
        gemm2_kernel<<<dim3(16, 16), 256>>>(r1, q1, 8);

        Seg r2 = mkseg(pR, pPc, nullptr, pR + 2 * NN, 2, NN, NN, NN, NN, 0, NN, 0, 1, nullptr);
        Seg q2 = mkseg(pPc, pPc, nullptr, pPd,        NN, NN, NN, NN, NN, 0, NN, 1, 1, nullptr);
        gemm2_kernel<<<dim3(16, 16), 256>>>(r2, q2, 8);

        Seg r4 = mkseg(pR, pPd, nullptr, pR + 4 * NN, 4, NN, NN, NN, NN, 0, NN, 0, 1, nullptr);
        Seg q4 = mkseg(pPd, pPd, nullptr, pPa,        NN, NN, NN, NN, NN, 0, NN, 1, 1, nullptr);
        gemm2_kernel<<<dim3(16, 16), 256>>>(r4, q4, 8);

        Seg r8 = mkseg(pR, pPa, nullptr, pR + 8 * NN, 8, NN, NN, NN, NN, 0, NN, 0, 1, nullptr);
        gemm1_kernel<<<dim3(8, 1), 256>>>(r8);
    }

    // 7. G = R @ V  and  Pp = R @ W (flag-guarded), one launch (dense x dense)
    {
        Seg sg = mkseg(pR, pV, nullptr, pG,  QQ, SS, NN, NN, SS, 0, SS, 0, 0, nullptr);
        Seg sp = mkseg(pR, pW, nullptr, pPp, QQ, SS, NN, NN, SS, 0, SS, 0, 0, pflag);
        gemm2_kernel<<<dim3(32, 1), 256>>>(sg, sp, 16);
    }

    // 8. Fold h0 into the scan: s_0 <- s_0 + PS @ h0 (skip if h0 == 0).
    matvec_kernel<<<64, 256>>>(PS, h0, pSmat, pSmat, QQ, QQ, pflag);

    // 9. Binary-tree chunk scan: h_L = sum_q PS^{15-q} s_q  (+ PS^16 h0 via fold)
    bool write_h = (out_size >= LL + NN);
    float* hdst = write_h ? (out + LL) : phA;
    {
        Seg l1 = mkseg(pPb, pSmat, pSmat + 8, pT1,  NN, 8, NN, NN, QQ, QQ, 8, 1, 0, nullptr);
        gemm1_kernel<<<dim3(1, 16), 256>>>(l1);
        Seg l2 = mkseg(pPc, pT1,   pT1 + 4,   pT2,  NN, 4, NN, NN, 8,  8,  4, 1, 0, nullptr);
        gemm1_kernel<<<dim3(1, 16), 256>>>(l2);
        Seg l3 = mkseg(pPd, pT2,   pT2 + 2,   pT3,  NN, 2, NN, NN, 4,  4,  2, 1, 0, nullptr);
        gemm1_kernel<<<dim3(1, 16), 256>>>(l3);
        Seg l4 = mkseg(pPa, pT3,   pT3 + 1,   hdst, NN, 1, NN, NN, 2,  2,  1, 1, 0, nullptr);
        gemm1_kernel<<<dim3(1, 16), 256>>>(l4);
    }

    // 10. Output convolution: k-sliced partials then combine with Pp
    conv_part_kernel<<<dim3(LL / CT, 4), CT>>>(pG, x, pCP);
    conv_combine_kernel<<<LL / 256, 256>>>(pCP, pPp, out);
}